// round 1
// baseline (speedup 1.0000x reference)
#include <cuda_runtime.h>
#include <cstdint>
#include <cstddef>

#define N_NODES 8192
#define DIM 256

constexpr int BM = 64;       // output rows per CTA
constexpr int BK = 32;       // k-chunk (j dimension)
constexpr int NT = 256;      // threads per CTA
constexpr int NCHUNK = N_NODES / BK;   // 256
constexpr int ASTR = 68;     // padded A-tile stride (bank-conflict relief, 16B aligned)

// ---------------- scratch (device globals; no allocation allowed) ----------------
__device__ float g_Wh[N_NODES * DIM];
__device__ float g_H[N_NODES * DIM];
__device__ float g_s[N_NODES];
__device__ float g_d[N_NODES];
__device__ float g_E[N_NODES];
__device__ float g_Ep[N_NODES];
__device__ float g_G[N_NODES];
__device__ float g_F[N_NODES];
__device__ float g_Fp[N_NODES];

// ---------------- small helpers ----------------
__device__ __forceinline__ unsigned long long pk2(float lo, float hi) {
    unsigned long long r;
    asm("mov.b64 %0, {%1, %2};" : "=l"(r) : "f"(lo), "f"(hi));
    return r;
}
__device__ __forceinline__ void upk2(unsigned long long v, float& lo, float& hi) {
    asm("mov.b64 {%0, %1}, %2;" : "=f"(lo), "=f"(hi) : "l"(v));
}
// packed dual fp32 FMA (Blackwell f32x2 pipe; ptxas never auto-fuses this)
__device__ __forceinline__ void fma2(unsigned long long& acc, unsigned long long a,
                                     unsigned long long b) {
    asm("fma.rn.f32x2 %0, %1, %2, %0;" : "+l"(acc) : "l"(a), "l"(b));
}
__device__ __forceinline__ void cpasync16(uint32_t saddr, const void* g) {
    asm volatile("cp.async.cg.shared.global [%0], [%1], 16;" :: "r"(saddr), "l"(g));
}
__device__ __forceinline__ void cpasync_commit() {
    asm volatile("cp.async.commit_group;");
}
__device__ __forceinline__ float elu1(float x) {
    return x > 0.0f ? x : expm1f(x);
}

// 64x256 += A(64x32) * B(32x256), register micro-tile 8x8 per thread via f32x2 pairs.
// As layout: As[kk*ASTR + r] (transposed). Bs layout: Bs[kk*256 + c].
__device__ __forceinline__ void mm_block(const float* As, const float* Bs,
                                         unsigned long long acc[32], int r0, int c0) {
#pragma unroll 8
    for (int kk = 0; kk < BK; ++kk) {
        float4 a0 = *reinterpret_cast<const float4*>(As + kk * ASTR + r0);
        float4 a1 = *reinterpret_cast<const float4*>(As + kk * ASTR + r0 + 4);
        float4 b0 = *reinterpret_cast<const float4*>(Bs + kk * DIM + c0);
        float4 b1 = *reinterpret_cast<const float4*>(Bs + kk * DIM + c0 + 4);
        unsigned long long ap[4];
        ap[0] = pk2(a0.x, a0.y);
        ap[1] = pk2(a0.z, a0.w);
        ap[2] = pk2(a1.x, a1.y);
        ap[3] = pk2(a1.z, a1.w);
        float bv[8] = {b0.x, b0.y, b0.z, b0.w, b1.x, b1.y, b1.z, b1.w};
#pragma unroll
        for (int n = 0; n < 8; ++n) {
            unsigned long long bb = pk2(bv[n], bv[n]);
#pragma unroll
            for (int m = 0; m < 4; ++m) fma2(acc[m * 8 + n], ap[m], bb);
        }
    }
}

// ---------------- Wh = X @ W  (M=8192, K=256, N=256) ----------------
__global__ __launch_bounds__(NT) void gemm_wh_kernel(const float* __restrict__ X,
                                                     const float* __restrict__ W,
                                                     float* __restrict__ out) {
    __shared__ float As[BK * ASTR];
    __shared__ float Bs[BK * DIM];
    int t = threadIdx.x;
    int i0 = blockIdx.x * BM;
    int tA_r = t >> 2, tA_c = t & 3;
    int tr = t >> 5, tc = t & 31;
    int r0 = tr * 8, c0 = tc * 8;
    unsigned long long acc[32];
#pragma unroll
    for (int i = 0; i < 32; ++i) acc[i] = 0ull;

    for (int p = 0; p < DIM / BK; ++p) {
        int k0 = p * BK;
        const float4* xsrc = reinterpret_cast<const float4*>(
            X + (size_t)(i0 + tA_r) * DIM + k0 + tA_c * 8);
        float4 x0 = xsrc[0], x1 = xsrc[1];
        __syncthreads();
        float xv[8] = {x0.x, x0.y, x0.z, x0.w, x1.x, x1.y, x1.z, x1.w};
#pragma unroll
        for (int u = 0; u < 8; ++u) As[(tA_c * 8 + u) * ASTR + tA_r] = xv[u];
        const float4* wsrc = reinterpret_cast<const float4*>(W + (size_t)k0 * DIM);
        float4* bdst = reinterpret_cast<float4*>(Bs);
#pragma unroll
        for (int k = 0; k < 8; ++k) bdst[t + k * NT] = wsrc[t + k * NT];
        __syncthreads();
        mm_block(As, Bs, acc, r0, c0);
    }

#pragma unroll
    for (int m = 0; m < 4; ++m) {
        int ra = r0 + 2 * m;
        float oa[8], ob[8];
#pragma unroll
        for (int n = 0; n < 8; ++n) upk2(acc[m * 8 + n], oa[n], ob[n]);
        float4* da = reinterpret_cast<float4*>(out + (size_t)(i0 + ra) * DIM + c0);
        float4* db = reinterpret_cast<float4*>(out + (size_t)(i0 + ra + 1) * DIM + c0);
        da[0] = make_float4(oa[0], oa[1], oa[2], oa[3]);
        da[1] = make_float4(oa[4], oa[5], oa[6], oa[7]);
        db[0] = make_float4(ob[0], ob[1], ob[2], ob[3]);
        db[1] = make_float4(ob[4], ob[5], ob[6], ob[7]);
    }
}

// ---------------- s = Wh@a_src, d = Wh@a_dst (one warp per row) ----------------
__global__ __launch_bounds__(NT) void rowdot_kernel(const float* __restrict__ Wh,
                                                    const float* __restrict__ asrc,
                                                    const float* __restrict__ adst,
                                                    float* __restrict__ s,
                                                    float* __restrict__ d) {
    int gw = (blockIdx.x * blockDim.x + threadIdx.x) >> 5;
    int lane = threadIdx.x & 31;
    if (gw >= N_NODES) return;
    const float* row = Wh + (size_t)gw * DIM;
    float ps = 0.0f, pd = 0.0f;
#pragma unroll
    for (int q = 0; q < 8; ++q) {
        float v = row[lane + 32 * q];
        ps = fmaf(v, asrc[lane + 32 * q], ps);
        pd = fmaf(v, adst[lane + 32 * q], pd);
    }
#pragma unroll
    for (int off = 16; off > 0; off >>= 1) {
        ps += __shfl_xor_sync(0xffffffffu, ps, off);
        pd += __shfl_xor_sync(0xffffffffu, pd, off);
    }
    if (lane == 0) { s[gw] = ps; d[gw] = pd; }
}

// ---------------- per-node softmax factors (single CTA) ----------------
// c = max(s)+max(d);  E=exp(s-c/2) Ep=exp(.2s-c/2) G=exp(-s-c/2) F=exp(d-c/2) Fp=exp(.2d-c/2)
__global__ __launch_bounds__(1024) void factors_kernel(const float* __restrict__ s,
                                                       const float* __restrict__ d,
                                                       float* __restrict__ E,
                                                       float* __restrict__ Ep,
                                                       float* __restrict__ G,
                                                       float* __restrict__ F,
                                                       float* __restrict__ Fp) {
    __shared__ float rs[1024];
    __shared__ float rd[1024];
    int t = threadIdx.x;
    float ms = -3.4e38f, md = -3.4e38f;
    for (int idx = t; idx < N_NODES; idx += 1024) {
        ms = fmaxf(ms, s[idx]);
        md = fmaxf(md, d[idx]);
    }
    rs[t] = ms; rd[t] = md;
    __syncthreads();
    for (int off = 512; off > 0; off >>= 1) {
        if (t < off) {
            rs[t] = fmaxf(rs[t], rs[t + off]);
            rd[t] = fmaxf(rd[t], rd[t + off]);
        }
        __syncthreads();
    }
    float h = 0.5f * (rs[0] + rd[0]);
    for (int idx = t; idx < N_NODES; idx += 1024) {
        float si = s[idx], di = d[idx];
        E[idx]  = expf(si - h);
        Ep[idx] = expf(0.2f * si - h);
        G[idx]  = expf(-si - h);
        F[idx]  = expf(di - h);
        Fp[idx] = expf(0.2f * di - h);
    }
}

// ---------------- main masked-softmax aggregation GEMM ----------------
// out[i,:] = elu( (sum_j w_ij * Wh[j,:]) / (sum_j w_ij) )
// smem (floats): F[8192] | Fp[8192] | Bs[2*8192] | As[2176] | Zs[64] | Zp[256]
constexpr int SM_F   = 0;
constexpr int SM_FP  = 8192;
constexpr int SM_BS  = 16384;
constexpr int SM_AS  = 32768;
constexpr int SM_ZS  = 32768 + BK * ASTR;          // 34944
constexpr int SM_ZP  = SM_ZS + 64;                 // 35008
constexpr int SMEM_FLOATS = SM_ZP + NT;            // 35264
constexpr int SMEM_BYTES  = SMEM_FLOATS * 4;       // 141056

__global__ __launch_bounds__(NT, 1) void gat_main_kernel(
    const int* __restrict__ adj, const float* __restrict__ Wh,
    const float* __restrict__ E, const float* __restrict__ Ep,
    const float* __restrict__ G, const float* __restrict__ F,
    const float* __restrict__ Fp, float* __restrict__ out) {
    extern __shared__ float sm[];
    float* Fbuf  = sm + SM_F;
    float* Fpbuf = sm + SM_FP;
    float* Bs    = sm + SM_BS;
    float* As    = sm + SM_AS;
    float* Zs    = sm + SM_ZS;
    float* Zp    = sm + SM_ZP;

    int t = threadIdx.x;
    int i0 = blockIdx.x * BM;
    int tA_r = t >> 2, tA_c = t & 3;
    int tr = t >> 5, tc = t & 31;
    int r0 = tr * 8, c0 = tc * 8;

    // preload F, Fp arrays (32 KB each) into smem
    {
        const float4* f4  = reinterpret_cast<const float4*>(F);
        const float4* fp4 = reinterpret_cast<const float4*>(Fp);
        float4* df  = reinterpret_cast<float4*>(Fbuf);
        float4* dfp = reinterpret_cast<float4*>(Fpbuf);
        for (int idx = t; idx < N_NODES / 4; idx += NT) {
            df[idx]  = f4[idx];
            dfp[idx] = fp4[idx];
        }
    }
    float Er  = E[i0 + tA_r];
    float Epr = Ep[i0 + tA_r];
    float Gr  = G[i0 + tA_r];
    const int* adjrow = adj + (size_t)(i0 + tA_r) * N_NODES + tA_c * 8;

    unsigned long long acc[32];
#pragma unroll
    for (int i = 0; i < 32; ++i) acc[i] = 0ull;
    float zpart = 0.0f;

    __syncthreads();   // Fbuf/Fpbuf visible

    // prologue: B chunk 0 via cp.async, adj chunk 0 to regs
    {
        uint32_t bsa = (uint32_t)__cvta_generic_to_shared(Bs);
        const float4* gsrc = reinterpret_cast<const float4*>(Wh);
#pragma unroll
        for (int k = 0; k < 8; ++k) {
            int idx = t + k * NT;
            cpasync16(bsa + idx * 16, gsrc + idx);
        }
        cpasync_commit();
    }
    int4 a0 = *reinterpret_cast<const int4*>(adjrow);
    int4 a1 = *reinterpret_cast<const int4*>(adjrow + 4);

    for (int p = 0; p < NCHUNK; ++p) {
        int cur = p & 1;
        // issue next B chunk into the other buffer
        if (p + 1 < NCHUNK) {
            uint32_t bsa = (uint32_t)__cvta_generic_to_shared(Bs + (cur ^ 1) * (BK * DIM));
            const float4* gsrc =
                reinterpret_cast<const float4*>(Wh + (size_t)(p + 1) * BK * DIM);
#pragma unroll
            for (int k = 0; k < 8; ++k) {
                int idx = t + k * NT;
                cpasync16(bsa + idx * 16, gsrc + idx);
            }
            cpasync_commit();
        }
        // build A tile (attention weights) for chunk p from adj regs + factors
        {
            int av[8] = {a0.x, a0.y, a0.z, a0.w, a1.x, a1.y, a1.z, a1.w};
            int jbase = p * BK + tA_c * 8;
#pragma unroll
            for (int u = 0; u < 8; ++u) {
                int j = jbase + u;
                float f = Fbuf[j], fp = Fpbuf[j];
                float w = (f > Gr) ? (Er * f) : (Epr * fp);
                w = (av[u] != 0) ? w : 0.0f;
                As[(tA_c * 8 + u) * ASTR + tA_r] = w;
                zpart += w;
            }
        }
        // prefetch adj chunk p+1 (latency hidden by the FMA block below)
        if (p + 1 < NCHUNK) {
            const int4* ap = reinterpret_cast<const int4*>(adjrow + (p + 1) * BK);
            a0 = ap[0];
            a1 = ap[1];
        }
        if (p + 1 < NCHUNK) {
            asm volatile("cp.async.wait_group 1;");
        } else {
            asm volatile("cp.async.wait_group 0;");
        }
        __syncthreads();   // A stores + B chunk p visible to all
        mm_block(As, Bs + cur * (BK * DIM), acc, r0, c0);
        __syncthreads();   // all reads done before buffers are overwritten
    }

    // deterministic Z reduction (4 partials per row, fixed order)
    Zp[t] = zpart;
    __syncthreads();
    if (t < BM) {
        Zs[t] = (Zp[t * 4 + 0] + Zp[t * 4 + 1]) + (Zp[t * 4 + 2] + Zp[t * 4 + 3]);
    }
    __syncthreads();

    // epilogue: divide by Z, ELU, store
#pragma unroll
    for (int m = 0; m < 4; ++m) {
        int ra = r0 + 2 * m;
        float za = 1.0f / Zs[ra];
        float zb = 1.0f / Zs[ra + 1];
        float oa[8], ob[8];
#pragma unroll
        for (int n = 0; n < 8; ++n) {
            float lo, hi;
            upk2(acc[m * 8 + n], lo, hi);
            oa[n] = elu1(lo * za);
            ob[n] = elu1(hi * zb);
        }
        float4* da = reinterpret_cast<float4*>(out + (size_t)(i0 + ra) * DIM + c0);
        float4* db = reinterpret_cast<float4*>(out + (size_t)(i0 + ra + 1) * DIM + c0);
        da[0] = make_float4(oa[0], oa[1], oa[2], oa[3]);
        da[1] = make_float4(oa[4], oa[5], oa[6], oa[7]);
        db[0] = make_float4(ob[0], ob[1], ob[2], ob[3]);
        db[1] = make_float4(ob[4], ob[5], ob[6], ob[7]);
    }
}

// ---------------- host orchestration ----------------
extern "C" void kernel_launch(void* const* d_in, const int* in_sizes, int n_in,
                              void* d_out, int out_size) {
    const float* V   = (const float*)d_in[0];
    const int*   adj = (const int*)d_in[1];
    const float* W1  = (const float*)d_in[2];
    const float* as1 = (const float*)d_in[3];
    const float* ad1 = (const float*)d_in[4];
    const float* W2  = (const float*)d_in[5];
    const float* as2 = (const float*)d_in[6];
    const float* ad2 = (const float*)d_in[7];
    float* out = (float*)d_out;

    float *Wh, *H, *s, *d, *E, *Ep, *G, *F, *Fp;
    cudaGetSymbolAddress((void**)&Wh, g_Wh);
    cudaGetSymbolAddress((void**)&H,  g_H);
    cudaGetSymbolAddress((void**)&s,  g_s);
    cudaGetSymbolAddress((void**)&d,  g_d);
    cudaGetSymbolAddress((void**)&E,  g_E);
    cudaGetSymbolAddress((void**)&Ep, g_Ep);
    cudaGetSymbolAddress((void**)&G,  g_G);
    cudaGetSymbolAddress((void**)&F,  g_F);
    cudaGetSymbolAddress((void**)&Fp, g_Fp);

    cudaFuncSetAttribute(gat_main_kernel,
                         cudaFuncAttributeMaxDynamicSharedMemorySize, SMEM_BYTES);

    // ---- layer 1 ----
    gemm_wh_kernel<<<N_NODES / BM, NT>>>(V, W1, Wh);
    rowdot_kernel<<<N_NODES * 32 / NT, NT>>>(Wh, as1, ad1, s, d);
    factors_kernel<<<1, 1024>>>(s, d, E, Ep, G, F, Fp);
    gat_main_kernel<<<N_NODES / BM, NT, SMEM_BYTES>>>(adj, Wh, E, Ep, G, F, Fp, H);

    // ---- layer 2 ----
    gemm_wh_kernel<<<N_NODES / BM, NT>>>(H, W2, Wh);
    rowdot_kernel<<<N_NODES * 32 / NT, NT>>>(Wh, as2, ad2, s, d);
    factors_kernel<<<1, 1024>>>(s, d, E, Ep, G, F, Fp);
    gat_main_kernel<<<N_NODES / BM, NT, SMEM_BYTES>>>(adj, Wh, E, Ep, G, F, Fp, out);
}

// round 4
// speedup vs baseline: 2.3254x; 2.3254x over previous
#include <cuda_runtime.h>
#include <cuda_bf16.h>
#include <cstdint>
#include <cstddef>

#define NN 8192
#define DIM 256

// ---------------- device-global scratch ----------------
__device__ float g_Wh[NN * DIM];
__device__ float g_H[NN * DIM];
__device__ float g_s[NN];
__device__ float g_d[NN];
__device__ float4 g_EEpG[NN];                 // (E, Ep, G, 0) per node
__device__ float2 g_FFp[NN];                  // (F, Fp) per node
__device__ __nv_bfloat16 g_BhT[DIM * NN];     // WhT hi  [dim][node]
__device__ __nv_bfloat16 g_BlT[DIM * NN];     // WhT lo
__device__ uint32_t g_adjP[NN * (NN / 32)];   // bit-packed adjacency

// ---------------- helpers ----------------
__device__ __forceinline__ void cpasync16(uint32_t saddr, const void* g) {
    asm volatile("cp.async.cg.shared.global [%0], [%1], 16;" :: "r"(saddr), "l"(g));
}
__device__ __forceinline__ void cpasync_commit() { asm volatile("cp.async.commit_group;"); }
__device__ __forceinline__ void cpasync_wait0() { asm volatile("cp.async.wait_group 0;"); }
__device__ __forceinline__ uint32_t swz(uint32_t off) { return off ^ ((off >> 3) & 0x70u); }
__device__ __forceinline__ float elu1(float x) { return x > 0.0f ? x : expm1f(x); }

__device__ __forceinline__ void ldsm4(uint32_t* r, uint32_t addr) {
    asm volatile("ldmatrix.sync.aligned.m8n8.x4.shared.b16 {%0,%1,%2,%3}, [%4];"
                 : "=r"(r[0]), "=r"(r[1]), "=r"(r[2]), "=r"(r[3]) : "r"(addr));
}
__device__ __forceinline__ void mma_bf16(float* c, const uint32_t* a, const uint32_t* b) {
    asm volatile(
        "mma.sync.aligned.m16n8k16.row.col.f32.bf16.bf16.f32 "
        "{%0,%1,%2,%3}, {%4,%5,%6,%7}, {%8,%9}, {%0,%1,%2,%3};"
        : "+f"(c[0]), "+f"(c[1]), "+f"(c[2]), "+f"(c[3])
        : "r"(a[0]), "r"(a[1]), "r"(a[2]), "r"(a[3]), "r"(b[0]), "r"(b[1]));
}

// f32x2 helpers for the feature GEMM
__device__ __forceinline__ unsigned long long pk2(float lo, float hi) {
    unsigned long long r;
    asm("mov.b64 %0, {%1, %2};" : "=l"(r) : "f"(lo), "f"(hi));
    return r;
}
__device__ __forceinline__ void upk2(unsigned long long v, float& lo, float& hi) {
    asm("mov.b64 {%0, %1}, %2;" : "=f"(lo), "=f"(hi) : "l"(v));
}
__device__ __forceinline__ void fma2(unsigned long long& acc, unsigned long long a,
                                     unsigned long long b) {
    asm("fma.rn.f32x2 %0, %1, %2, %0;" : "+l"(acc) : "l"(a), "l"(b));
}

// ================= adj bit-pack =================
__global__ __launch_bounds__(256) void pack_adj_kernel(const int* __restrict__ adj,
                                                       uint32_t* __restrict__ adjP) {
    int warpId = (blockIdx.x * 256 + threadIdx.x) >> 5;
    int lane = threadIdx.x & 31;
    const int* base = adj + (size_t)warpId * 1024;
    uint32_t w = 0;
#pragma unroll
    for (int k = 0; k < 32; ++k) {
        uint32_t b = __ballot_sync(0xffffffffu, base[k * 32 + lane] != 0);
        if (lane == k) w = b;
    }
    adjP[(size_t)warpId * 32 + lane] = w;
}

// ================= Wh = X @ W (SIMT f32x2, validated round 1) =================
constexpr int GW_BM = 64, GW_BK = 32, GW_NT = 256, GW_ASTR = 68;

__device__ __forceinline__ void mm_block(const float* As, const float* Bs,
                                         unsigned long long acc[32], int r0, int c0) {
#pragma unroll 8
    for (int kk = 0; kk < GW_BK; ++kk) {
        float4 a0 = *reinterpret_cast<const float4*>(As + kk * GW_ASTR + r0);
        float4 a1 = *reinterpret_cast<const float4*>(As + kk * GW_ASTR + r0 + 4);
        float4 b0 = *reinterpret_cast<const float4*>(Bs + kk * DIM + c0);
        float4 b1 = *reinterpret_cast<const float4*>(Bs + kk * DIM + c0 + 4);
        unsigned long long ap[4];
        ap[0] = pk2(a0.x, a0.y); ap[1] = pk2(a0.z, a0.w);
        ap[2] = pk2(a1.x, a1.y); ap[3] = pk2(a1.z, a1.w);
        float bv[8] = {b0.x, b0.y, b0.z, b0.w, b1.x, b1.y, b1.z, b1.w};
#pragma unroll
        for (int n = 0; n < 8; ++n) {
            unsigned long long bb = pk2(bv[n], bv[n]);
#pragma unroll
            for (int m = 0; m < 4; ++m) fma2(acc[m * 8 + n], ap[m], bb);
        }
    }
}

__global__ __launch_bounds__(GW_NT) void gemm_wh_kernel(const float* __restrict__ X,
                                                        const float* __restrict__ W,
                                                        float* __restrict__ out) {
    __shared__ float As[GW_BK * GW_ASTR];
    __shared__ float Bs[GW_BK * DIM];
    int t = threadIdx.x;
    int i0 = blockIdx.x * GW_BM;
    int tA_r = t >> 2, tA_c = t & 3;
    int tr = t >> 5, tc = t & 31;
    int r0 = tr * 8, c0 = tc * 8;
    unsigned long long acc[32];
#pragma unroll
    for (int i = 0; i < 32; ++i) acc[i] = 0ull;

    for (int p = 0; p < DIM / GW_BK; ++p) {
        int k0 = p * GW_BK;
        const float4* xsrc = reinterpret_cast<const float4*>(
            X + (size_t)(i0 + tA_r) * DIM + k0 + tA_c * 8);
        float4 x0 = xsrc[0], x1 = xsrc[1];
        __syncthreads();
        float xv[8] = {x0.x, x0.y, x0.z, x0.w, x1.x, x1.y, x1.z, x1.w};
#pragma unroll
        for (int u = 0; u < 8; ++u) As[(tA_c * 8 + u) * GW_ASTR + tA_r] = xv[u];
        const float4* wsrc = reinterpret_cast<const float4*>(W + (size_t)k0 * DIM);
        float4* bdst = reinterpret_cast<float4*>(Bs);
#pragma unroll
        for (int k = 0; k < 8; ++k) bdst[t + k * GW_NT] = wsrc[t + k * GW_NT];
        __syncthreads();
        mm_block(As, Bs, acc, r0, c0);
    }
#pragma unroll
    for (int m = 0; m < 4; ++m) {
        int ra = r0 + 2 * m;
        float oa[8], ob[8];
#pragma unroll
        for (int n = 0; n < 8; ++n) upk2(acc[m * 8 + n], oa[n], ob[n]);
        float4* da = reinterpret_cast<float4*>(out + (size_t)(i0 + ra) * DIM + c0);
        float4* db = reinterpret_cast<float4*>(out + (size_t)(i0 + ra + 1) * DIM + c0);
        da[0] = make_float4(oa[0], oa[1], oa[2], oa[3]);
        da[1] = make_float4(oa[4], oa[5], oa[6], oa[7]);
        db[0] = make_float4(ob[0], ob[1], ob[2], ob[3]);
        db[1] = make_float4(ob[4], ob[5], ob[6], ob[7]);
    }
}

// ================= transpose + bf16 split: Wh -> WhT hi/lo =================
__global__ __launch_bounds__(256) void trans_split_kernel(const float* __restrict__ Wh,
                                                          __nv_bfloat16* __restrict__ hiT,
                                                          __nv_bfloat16* __restrict__ loT) {
    __shared__ float tile[64][65];
    int t = threadIdx.x;
    int n0 = blockIdx.x * 64;
    int d0 = blockIdx.y * 64;
#pragma unroll
    for (int u = 0; u < 16; ++u) {
        int idx = t + u * 256;
        int r = idx >> 6, c = idx & 63;
        tile[r][c] = Wh[(size_t)(n0 + r) * DIM + d0 + c];
    }
    __syncthreads();
#pragma unroll
    for (int u = 0; u < 8; ++u) {
        int idx = t + u * 256;
        int dd = idx >> 5, np = idx & 31;
        float w0 = tile[np * 2][dd];
        float w1 = tile[np * 2 + 1][dd];
        __nv_bfloat162 h2 = __floats2bfloat162_rn(w0, w1);
        float l0 = w0 - __low2float(h2);
        float l1 = w1 - __high2float(h2);
        __nv_bfloat162 lo2 = __floats2bfloat162_rn(l0, l1);
        size_t off = (size_t)(d0 + dd) * NN + n0 + np * 2;
        *reinterpret_cast<__nv_bfloat162*>(hiT + off) = h2;
        *reinterpret_cast<__nv_bfloat162*>(loT + off) = lo2;
    }
}

// ================= s = Wh@a_src, d = Wh@a_dst =================
__global__ __launch_bounds__(256) void rowdot_kernel(const float* __restrict__ Wh,
                                                     const float* __restrict__ asrc,
                                                     const float* __restrict__ adst,
                                                     float* __restrict__ s,
                                                     float* __restrict__ d) {
    int gw = (blockIdx.x * blockDim.x + threadIdx.x) >> 5;
    int lane = threadIdx.x & 31;
    if (gw >= NN) return;
    const float* row = Wh + (size_t)gw * DIM;
    float ps = 0.0f, pd = 0.0f;
#pragma unroll
    for (int q = 0; q < 8; ++q) {
        float v = row[lane + 32 * q];
        ps = fmaf(v, asrc[lane + 32 * q], ps);
        pd = fmaf(v, adst[lane + 32 * q], pd);
    }
#pragma unroll
    for (int off = 16; off > 0; off >>= 1) {
        ps += __shfl_xor_sync(0xffffffffu, ps, off);
        pd += __shfl_xor_sync(0xffffffffu, pd, off);
    }
    if (lane == 0) { s[gw] = ps; d[gw] = pd; }
}

// ================= per-node softmax factors =================
__global__ __launch_bounds__(1024) void factors_kernel(const float* __restrict__ s,
                                                       const float* __restrict__ d,
                                                       float4* __restrict__ EEpG,
                                                       float2* __restrict__ FFp) {
    __shared__ float rs[1024];
    __shared__ float rd[1024];
    int t = threadIdx.x;
    float ms = -3.4e38f, md = -3.4e38f;
    for (int idx = t; idx < NN; idx += 1024) {
        ms = fmaxf(ms, s[idx]);
        md = fmaxf(md, d[idx]);
    }
    rs[t] = ms; rd[t] = md;
    __syncthreads();
    for (int off = 512; off > 0; off >>= 1) {
        if (t < off) {
            rs[t] = fmaxf(rs[t], rs[t + off]);
            rd[t] = fmaxf(rd[t], rd[t + off]);
        }
        __syncthreads();
    }
    float hh = 0.5f * (rs[0] + rd[0]);
    for (int idx = t; idx < NN; idx += 1024) {
        float si = s[idx], di = d[idx];
        EEpG[idx] = make_float4(expf(si - hh), expf(0.2f * si - hh), expf(-si - hh), 0.0f);
        FFp[idx] = make_float2(expf(di - hh), expf(0.2f * di - hh));
    }
}

// ================= mma.sync aggregation: out = elu((A @ WhT^T)/Z) =================
// CTA: 128 rows x 128 dims, K chunks of 64. 8 warps: warp (rg = w&3, cg = w>>2)
// owns a 32x64 output tile. A tile 128x64 bf16 hi/lo built in smem from factors.
constexpr int KC = 64;
constexpr int NCH = NN / KC;   // 128
// smem byte offsets (16 KB tiles, double buffered)
__device__ __forceinline__ uint32_t AHOF(int b) { return (uint32_t)b * 16384u; }
__device__ __forceinline__ uint32_t ALOF(int b) { return 32768u + (uint32_t)b * 16384u; }
__device__ __forceinline__ uint32_t BHOF(int b) { return 65536u + (uint32_t)b * 16384u; }
__device__ __forceinline__ uint32_t BLOF(int b) { return 98304u + (uint32_t)b * 16384u; }
constexpr int SM_F2 = 131072;          // float2[8192] = 64 KB
constexpr int SM_ZP = 196608;          // float[256]
constexpr int SM_ZS = 197632;          // float[128]
constexpr int GAT_SMEM = 198144;

__global__ __launch_bounds__(256, 1) void gat_mma_kernel(
    const uint32_t* __restrict__ adjP,
    const __nv_bfloat16* __restrict__ BhT, const __nv_bfloat16* __restrict__ BlT,
    const float4* __restrict__ EEpG, const float2* __restrict__ FFp,
    float* __restrict__ out) {
    extern __shared__ __align__(1024) char sm[];
    uint32_t sb = (uint32_t)__cvta_generic_to_shared(sm);
    int t = threadIdx.x, wid = t >> 5, lane = t & 31;
    int rb = blockIdx.x >> 1, h = blockIdx.x & 1, i0 = rb * 128;
    int rg = wid & 3, cg = wid >> 2;

    // preload (F, Fp) pairs into smem
    {
        const float4* src = reinterpret_cast<const float4*>(FFp);
        float4* dst = reinterpret_cast<float4*>(sm + SM_F2);
        for (int idx = t; idx < NN / 2; idx += 256) dst[idx] = src[idx];
    }
    // per-thread build state: row r, col half
    int r = t >> 1;
    int colbase = (t & 1) * 32;
    float4 eg = EEpG[i0 + r];
    float E = eg.x, Ep = eg.y, G = eg.z;
    const uint32_t* wp = adjP + (size_t)(i0 + r) * (NN / 32) + (t & 1);
    const float2* F2 = reinterpret_cast<const float2*>(sm + SM_F2);
    uint32_t aByte = (uint32_t)(r * 128 + colbase * 2);
    const __nv_bfloat16* srcH = BhT + (size_t)h * 128 * NN;
    const __nv_bfloat16* srcL = BlT + (size_t)h * 128 * NN;

    float c[16][4];   // [mt*8 + nt][4]
#pragma unroll
    for (int i = 0; i < 16; ++i)
#pragma unroll
        for (int j = 0; j < 4; ++j) c[i][j] = 0.0f;
    float zpart = 0.0f;

    // prologue: B chunk 0
#pragma unroll
    for (int k = 0; k < 4; ++k) {
        int id = t + 256 * k;
        int n = id >> 3, u = id & 7;
        uint32_t dsw = swz((uint32_t)(n * 128 + u * 16));
        cpasync16(sb + BHOF(0) + dsw, srcH + (size_t)n * NN + u * 8);
        cpasync16(sb + BLOF(0) + dsw, srcL + (size_t)n * NN + u * 8);
    }
    cpasync_commit();
    __syncthreads();   // F2 visible

    for (int p = 0; p < NCH; ++p) {
        int buf = p & 1;
        cpasync_wait0();   // own B[p] slice arrived
        // ---- build A[p] (hi/lo split) ----
        {
            uint32_t aw = wp[2 * p];
            const float4* fj4 =
                reinterpret_cast<const float4*>(F2 + p * KC + colbase);
            char* ah = sm + AHOF(buf);
            char* al = sm + ALOF(buf);
#pragma unroll
            for (int u = 0; u < 16; ++u) {
                float4 f4 = fj4[u];
                float w0 = (f4.x > G) ? E * f4.x : Ep * f4.y;
                float w1 = (f4.z > G) ? E * f4.z : Ep * f4.w;
                w0 = ((aw >> (2 * u)) & 1u) ? w0 : 0.0f;
                w1 = ((aw >> (2 * u + 1)) & 1u) ? w1 : 0.0f;
                zpart += w0 + w1;
                __nv_bfloat162 h2 = __floats2bfloat162_rn(w0, w1);
                float l0 = w0 - __low2float(h2);
                float l1 = w1 - __high2float(h2);
                __nv_bfloat162 l2 = __floats2bfloat162_rn(l0, l1);
                uint32_t off = swz(aByte + 4u * u);
                *reinterpret_cast<uint32_t*>(ah + off) = *reinterpret_cast<uint32_t*>(&h2);
                *reinterpret_cast<uint32_t*>(al + off) = *reinterpret_cast<uint32_t*>(&l2);
            }
        }
        __syncthreads();   // A[p] + all B[p] slices visible; all reads of buf^1 done
        // ---- issue B[p+1] into other buffer (post-sync: safe) ----
        if (p + 1 < NCH) {
#pragma unroll
            for (int k = 0; k < 4; ++k) {
                int id = t + 256 * k;
                int n = id >> 3, u = id & 7;
                uint32_t dsw = swz((uint32_t)(n * 128 + u * 16));
                const size_t gofs = (size_t)n * NN + (size_t)(p + 1) * KC + u * 8;
                cpasync16(sb + BHOF(buf ^ 1) + dsw, srcH + gofs);
                cpasync16(sb + BLOF(buf ^ 1) + dsw, srcL + gofs);
            }
            cpasync_commit();
        }
        // ---- consume: ldmatrix + mma ----
        uint32_t bAh = sb + AHOF(buf), bAl = sb + ALOF(buf);
        uint32_t bBh = sb + BHOF(buf), bBl = sb + BLOF(buf);
#pragma unroll
        for (int ks = 0; ks < 4; ++ks) {
            int k0 = ks * 16;
            uint32_t ah[2][4], al[2][4];
#pragma unroll
            for (int mt = 0; mt < 2; ++mt) {
                int row = rg * 32 + mt * 16 + (lane & 15);
                int kc = k0 + (lane >> 4) * 8;
                uint32_t off = swz((uint32_t)(row * 128 + kc * 2));
                ldsm4(ah[mt], bAh + off);
                ldsm4(al[mt], bAl + off);
            }
#pragma unroll
            for (int np = 0; np < 4; ++np) {
                int n0 = cg * 64 + np * 16;
                int nrow = n0 + (lane & 7) + (lane >> 4) * 8;
                int kc = k0 + ((lane >> 3) & 1) * 8;
                uint32_t off = swz((uint32_t)(nrow * 128 + kc * 2));
                uint32_t bh[4], bl[4];
                ldsm4(bh, bBh + off);
                ldsm4(bl, bBl + off);
#pragma unroll
                for (int mt = 0; mt < 2; ++mt) {
#pragma unroll
                    for (int nt = 0; nt < 2; ++nt) {
                        float* cc = c[mt * 8 + np * 2 + nt];
                        mma_bf16(cc, ah[mt], bh + nt * 2);
                        mma_bf16(cc, ah[mt], bl + nt * 2);
                        mma_bf16(cc, al[mt], bh + nt * 2);
                    }
                }
            }
        }
    }

    // ---- deterministic Z reduction ----
    float* Zp = reinterpret_cast<float*>(sm + SM_ZP);
    float* Zs = reinterpret_cast<float*>(sm + SM_ZS);
    Zp[t] = zpart;
    __syncthreads();
    if (t < 128) Zs[t] = Zp[2 * t] + Zp[2 * t + 1];
    __syncthreads();

    // ---- epilogue: /Z, ELU, store ----
#pragma unroll
    for (int mt = 0; mt < 2; ++mt) {
        int lr0 = rg * 32 + mt * 16 + (lane >> 2);
        float rz0 = 1.0f / Zs[lr0];
        float rz1 = 1.0f / Zs[lr0 + 8];
        float* row0 = out + (size_t)(i0 + lr0) * DIM + h * 128 + cg * 64 + 2 * (lane & 3);
        float* row1 = row0 + (size_t)8 * DIM;
#pragma unroll
        for (int nt = 0; nt < 8; ++nt) {
            const float* cc = c[mt * 8 + nt];
            float2 v0 = make_float2(elu1(cc[0] * rz0), elu1(cc[1] * rz0));
            float2 v1 = make_float2(elu1(cc[2] * rz1), elu1(cc[3] * rz1));
            *reinterpret_cast<float2*>(row0 + nt * 8) = v0;
            *reinterpret_cast<float2*>(row1 + nt * 8) = v1;
        }
    }
}

// ================= host orchestration =================
extern "C" void kernel_launch(void* const* d_in, const int* in_sizes, int n_in,
                              void* d_out, int out_size) {
    const float* V   = (const float*)d_in[0];
    const int*   adj = (const int*)d_in[1];
    const float* W1  = (const float*)d_in[2];
    const float* as1 = (const float*)d_in[3];
    const float* ad1 = (const float*)d_in[4];
    const float* W2  = (const float*)d_in[5];
    const float* as2 = (const float*)d_in[6];
    const float* ad2 = (const float*)d_in[7];
    float* out = (float*)d_out;

    float *Wh, *H, *s, *d;
    float4* EEpG;
    float2* FFp;
    __nv_bfloat16 *BhT, *BlT;
    uint32_t* adjP;
    cudaGetSymbolAddress((void**)&Wh, g_Wh);
    cudaGetSymbolAddress((void**)&H, g_H);
    cudaGetSymbolAddress((void**)&s, g_s);
    cudaGetSymbolAddress((void**)&d, g_d);
    cudaGetSymbolAddress((void**)&EEpG, g_EEpG);
    cudaGetSymbolAddress((void**)&FFp, g_FFp);
    cudaGetSymbolAddress((void**)&BhT, g_BhT);
    cudaGetSymbolAddress((void**)&BlT, g_BlT);
    cudaGetSymbolAddress((void**)&adjP, g_adjP);

    cudaFuncSetAttribute(gat_mma_kernel,
                         cudaFuncAttributeMaxDynamicSharedMemorySize, GAT_SMEM);

    pack_adj_kernel<<<8192, 256>>>(adj, adjP);

    // layer 1
    gemm_wh_kernel<<<NN / GW_BM, GW_NT>>>(V, W1, Wh);
    trans_split_kernel<<<dim3(128, 4), 256>>>(Wh, BhT, BlT);
    rowdot_kernel<<<NN * 32 / 256, 256>>>(Wh, as1, ad1, s, d);
    factors_kernel<<<1, 1024>>>(s, d, EEpG, FFp);
    gat_mma_kernel<<<128, 256, GAT_SMEM>>>(adjP, BhT, BlT, EEpG, FFp, H);

    // layer 2
    gemm_wh_kernel<<<NN / GW_BM, GW_NT>>>(H, W2, Wh);
    trans_split_kernel<<<dim3(128, 4), 256>>>(Wh, BhT, BlT);
    rowdot_kernel<<<NN * 32 / 256, 256>>>(Wh, as2, ad2, s, d);
    factors_kernel<<<1, 1024>>>(s, d, EEpG, FFp);
    gat_mma_kernel<<<128, 256, GAT_SMEM>>>(adjP, BhT, BlT, EEpG, FFp, out);
}